// round 7
// baseline (speedup 1.0000x reference)
#include <cuda_runtime.h>
#include <math.h>

// ---------------- problem dims ----------------
#define T_STEPS   128
#define IN_DIM    512
#define C_INT     8
#define ISQ       16
#define DIMN      256
#define NCH       8
#define OUT_CH    16
#define EMB_OUT   2048          // C_INT*ISQ*ISQ

// ---------------- scratch (static device globals; no allocs) ----------------
__device__ float g_WT[IN_DIM * EMB_OUT];       // W_embed transposed: [k][o]
__device__ float g_v[T_STEPS * EMB_OUT];       // masked coarse activations
__device__ float g_Z[2][NCH * DIMN * DIMN];    // ping-pong reservoir state
__device__ int   g_flag[128 * 32];             // per-block step flags (128B stride)

// dynamic smem layout (floats): tile 24*264 | wdecT 16*16*8 | woutT 32*260
#define OFF_TILE  0
#define OFF_WDEC  (24 * 264)                   // 6336
#define OFF_WOUT  (OFF_WDEC + 2048)            // 8384
#define SMEM_FLOATS (OFF_WOUT + 32 * 260)      // 16704 -> 66816 bytes

// ---------------- fast tanh: 1 - 2/(e^{2x}+1) ----------------
__device__ __forceinline__ float ftanh(float s) {
    float e = __expf(s + s);
    return 1.f - __fdividef(2.f, e + 1.f);
}

// ---------------- W_embed transpose (tiled, conflict-free) ----------------
__global__ void k_transpose(const float* __restrict__ W) {
    __shared__ float tile[32][33];
    int ob = blockIdx.x * 32;
    int kb = blockIdx.y * 32;
    int tx = threadIdx.x, ty = threadIdx.y;
#pragma unroll
    for (int i = 0; i < 4; i++)
        tile[ty + 8 * i][tx] = W[(ob + ty + 8 * i) * IN_DIM + kb + tx];
    __syncthreads();
#pragma unroll
    for (int i = 0; i < 4; i++)
        g_WT[(kb + ty + 8 * i) * EMB_OUT + ob + tx] = tile[tx][ty + 8 * i];
}

// ---------------- embed GEMM: v[t][o] = (X[t,:]·W[o,:]) * mask_coarse ------
__global__ __launch_bounds__(256) void k_embed(const float* __restrict__ X,
                                               const float* __restrict__ maskc) {
    __shared__ float sX[16 * IN_DIM];
    int tt0 = blockIdx.x * 16;
    int ob  = blockIdx.y * 256;
    for (int idx = threadIdx.x; idx < 16 * IN_DIM; idx += 256)
        sX[idx] = X[(tt0 + (idx >> 9)) * IN_DIM + (idx & 511)];
    __syncthreads();

    int to = threadIdx.x & 63;
    int tg = threadIdx.x >> 6;
    float acc[4][4];
#pragma unroll
    for (int a = 0; a < 4; a++)
#pragma unroll
        for (int b = 0; b < 4; b++) acc[a][b] = 0.f;

    for (int k = 0; k < IN_DIM; k++) {
        float w[4];
#pragma unroll
        for (int oi = 0; oi < 4; oi++)
            w[oi] = g_WT[k * EMB_OUT + ob + to + 64 * oi];
#pragma unroll
        for (int ti = 0; ti < 4; ti++) {
            float xv = sX[(tg * 4 + ti) * IN_DIM + k];
#pragma unroll
            for (int oi = 0; oi < 4; oi++) acc[ti][oi] += xv * w[oi];
        }
    }
#pragma unroll
    for (int ti = 0; ti < 4; ti++)
#pragma unroll
        for (int oi = 0; oi < 4; oi++) {
            int t = tt0 + tg * 4 + ti;
            int o = ob + to + 64 * oi;
            g_v[t * EMB_OUT + o] = acc[ti][oi] * maskc[o & 255];
        }
}

// ---------------- init output with bias (d_out is poisoned) ----------------
__global__ void k_init_out(float* __restrict__ y, const float* __restrict__ b) {
    int idx = blockIdx.x * 256 + threadIdx.x;
    if (idx < T_STEPS * 1024) y[idx] = b[(idx >> 6) & 15];
}

// ---------------- zero initial state + flags ----------------
__global__ void k_zero() {
    int idx = blockIdx.x * 256 + threadIdx.x;
    if (idx < 128 * 32) g_flag[idx] = 0;
    if (idx < NCH * DIMN * DIMN) g_Z[0][idx] = 0.f;
}

// ---------------- persistent reservoir scan + fused readout ----------------
// grid = 128 blocks (1/SM, single wave): block -> (channel c = b>>4, 16 rows)
// 512 threads: x = tid&255 (column), half = tid>>8 -> rows r0+half*8 .. +7
__global__ __launch_bounds__(512, 1) void k_scan(
    const float* __restrict__ maskf, const float* __restrict__ Wd,
    const float* __restrict__ w1g,  const float* __restrict__ w2g,
    const float* __restrict__ wog,  float* __restrict__ yout)
{
    const int blk = blockIdx.x;
    const int c   = blk >> 4;
    const int g   = blk & 15;
    const int r0  = g << 4;            // 16 rows per block
    const int tid = threadIdx.x;
    const int x   = tid & 255;
    const int h8  = (tid >> 8) << 3;   // 0 or 8

    const int prev = (c << 4) | ((g + 15) & 15);
    const int next = (c << 4) | ((g + 1) & 15);

    extern __shared__ __align__(16) float smem[];
    float (*s_tile)[264] = (float(*)[264])(smem + OFF_TILE); // rows r0-4..r0+19
    float* s_wdecT = smem + OFF_WDEC;   // [al(16)][b16(16)][ci(8)]
    float* s_woutT = smem + OFF_WOUT;   // [xl(32)] stride 260: [R(16)*16+oc]

    // ---- one-time staging ----
    for (int idx = tid; idx < 24 * 264; idx += 512)
        (smem + OFF_TILE)[idx] = 0.f;
    for (int idx = tid; idx < 2048; idx += 512) {
        int ci = idx & 7, b16 = (idx >> 3) & 15, al = idx >> 7;
        s_wdecT[idx] = Wd[ci * 2048 + c * 256 + al * 16 + b16];
    }
    for (int idx = tid; idx < 8192; idx += 512) {
        int oc = idx & 15, R = (idx >> 4) & 15, xl2 = idx >> 8;
        s_woutT[xl2 * 260 + R * 16 + oc] =
            wog[oc * 8192 + c * 1024 + ((r0 & 31) + R) * 32 + xl2];
    }
    float w1[9], w2[25], maskreg[8];
#pragma unroll
    for (int i = 0; i < 9; i++)  w1[i] = 0.9f * w1g[c * 9 + i];
#pragma unroll
    for (int i = 0; i < 25; i++) w2[i] = 0.1f * w2g[c * 25 + i];
#pragma unroll
    for (int r = 0; r < 8; r++)  maskreg[r] = maskf[(r0 + h8 + r) * 256 + x];

    const int jv  = x >> 4;
    const int b16 = x & 15;
    const int xl  = x & 31;
    const int iy  = r0 >> 5;
    const int jw  = x >> 5;
    const int ic  = r0 >> 4;          // one coarse row per block
    const int sc  = x + 4;

    __syncthreads();

    for (int t = 0; t < T_STEPS; t++) {
        const float* __restrict__ Zc   = g_Z[t & 1] + c * 65536;
        float* __restrict__       Znew = g_Z[(t & 1) ^ 1] + c * 65536;

        float vr[8];
#pragma unroll
        for (int ci = 0; ci < 8; ci++)
            vr[ci] = __ldg(&g_v[t * EMB_OUT + ci * 256 + ic * 16 + jv]);

        if (t > 0) {
            if (tid < 2) {
                volatile int* f = &g_flag[(tid == 0 ? prev : next) * 32];
                while (*f < t) { }
                __threadfence();
            }
            __syncthreads();
            // stage ONLY halo rows: tile rows 0..3 (r0-4..r0-1), 20..23 (r0+16..r0+19)
            for (int idx = tid; idx < 8 * 264; idx += 512) {
                int rr  = idx / 264, sc2 = idx - rr * 264;
                int tr  = rr < 4 ? rr : rr + 16;
                int grr = (r0 - 4 + tr) & 255;
                int gc  = (sc2 - 4) & 255;
                s_tile[tr][sc2] = __ldcg(&Zc[grr * 256 + gc]);
            }
            __syncthreads();
        }

        // ---- rolling depthwise convs over this half's 16 source rows ----
        float acc[8];
#pragma unroll
        for (int r = 0; r < 8; r++) acc[r] = 0.f;

#pragma unroll
        for (int rr = 0; rr < 16; rr++) {
            const int tr = h8 + rr;
            float t0 = s_tile[tr][sc - 4];
            float t1 = s_tile[tr][sc - 2];
            float t2 = s_tile[tr][sc];
            float t3 = s_tile[tr][sc + 2];
            float t4 = s_tile[tr][sc + 4];
#pragma unroll
            for (int a = 0; a < 5; a++) {
                int r = rr - 2 * a;
                if (r >= 0 && r < 8)
                    acc[r] += t0 * w2[a * 5 + 0] + t1 * w2[a * 5 + 1]
                            + t2 * w2[a * 5 + 2] + t3 * w2[a * 5 + 3]
                            + t4 * w2[a * 5 + 4];
            }
            if (rr >= 3 && rr <= 12) {
                float u0 = s_tile[tr][sc - 1];
                float u2 = s_tile[tr][sc + 1];
#pragma unroll
                for (int a = 0; a < 3; a++) {
                    int r = rr - 3 - a;
                    if (r >= 0 && r < 8)
                        acc[r] += u0 * w1[a * 3 + 0] + t2 * w1[a * 3 + 1]
                                + u2 * w1[a * 3 + 2];
                }
            }
        }

        __syncthreads();   // all tile reads done before z overwrites own rows

        // ---- per-row: deconv input, tanh, smem+global store, readout ----
        float accro[16];
#pragma unroll
        for (int oc = 0; oc < 16; oc++) accro[oc] = 0.f;

#pragma unroll
        for (int r = 0; r < 8; r++) {
            const int R = h8 + r;       // local row 0..15
            const float4 wA = *(const float4*)&s_wdecT[R * 128 + b16 * 8];
            const float4 wB = *(const float4*)&s_wdecT[R * 128 + b16 * 8 + 4];
            float uv = vr[0] * wA.x + vr[1] * wA.y + vr[2] * wA.z + vr[3] * wA.w
                     + vr[4] * wB.x + vr[5] * wB.y + vr[6] * wB.z + vr[7] * wB.w;

            float z = ftanh(acc[r] + uv * maskreg[r]);

            s_tile[4 + R][sc] = z;
            if (x < 4)    s_tile[4 + R][x + 260] = z;
            if (x >= 252) s_tile[4 + R][x - 252] = z;
            __stcg(&Znew[(r0 + R) * 256 + x], z);

            const float4 o0 = *(const float4*)&s_woutT[xl * 260 + R * 16 + 0];
            const float4 o1 = *(const float4*)&s_woutT[xl * 260 + R * 16 + 4];
            const float4 o2 = *(const float4*)&s_woutT[xl * 260 + R * 16 + 8];
            const float4 o3 = *(const float4*)&s_woutT[xl * 260 + R * 16 + 12];
            accro[0]  += z * o0.x;  accro[1]  += z * o0.y;
            accro[2]  += z * o0.z;  accro[3]  += z * o0.w;
            accro[4]  += z * o1.x;  accro[5]  += z * o1.y;
            accro[6]  += z * o1.z;  accro[7]  += z * o1.w;
            accro[8]  += z * o2.x;  accro[9]  += z * o2.y;
            accro[10] += z * o2.z;  accro[11] += z * o2.w;
            accro[12] += z * o3.x;  accro[13] += z * o3.y;
            accro[14] += z * o3.z;  accro[15] += z * o3.w;
        }

        // warp-level readout reduction (one 32-col band per warp)
#pragma unroll
        for (int oc = 0; oc < 16; oc++) {
            float v = accro[oc];
            v += __shfl_xor_sync(0xffffffffu, v, 16);
            v += __shfl_xor_sync(0xffffffffu, v, 8);
            v += __shfl_xor_sync(0xffffffffu, v, 4);
            v += __shfl_xor_sync(0xffffffffu, v, 2);
            v += __shfl_xor_sync(0xffffffffu, v, 1);
            if ((x & 31) == 0)
                atomicAdd(&yout[t * 1024 + oc * 64 + iy * 8 + jw], v);
        }

        __syncthreads();   // halo reads + z stores complete block-wide

        if (t < T_STEPS - 1 && tid == 0) {
            __threadfence();
            *(volatile int*)&g_flag[blk * 32] = t + 1;
        }
    }
}

// ---------------- launcher (graph-capturable, alloc-free) ----------------
extern "C" void kernel_launch(void* const* d_in, const int* in_sizes, int n_in,
                              void* d_out, int out_size)
{
    const float* X           = (const float*)d_in[0];  // [128,512]
    const float* W_embed     = (const float*)d_in[1];  // [2048,512]
    const float* mask_coarse = (const float*)d_in[2];  // [16,16]
    const float* mask_fine   = (const float*)d_in[3];  // [256,256]
    const float* W_deconv    = (const float*)d_in[4];  // [8,8,16,16]
    const float* w1          = (const float*)d_in[5];  // [8,1,3,3]
    const float* w2          = (const float*)d_in[6];  // [8,1,5,5]
    const float* w_out       = (const float*)d_in[7];  // [16,8,32,32]
    const float* b_out       = (const float*)d_in[8];  // [16]
    float* y = (float*)d_out;                          // [128,1024]

    cudaFuncSetAttribute(k_scan, cudaFuncAttributeMaxDynamicSharedMemorySize,
                         SMEM_FLOATS * 4);

    k_transpose<<<dim3(64, 16), dim3(32, 8)>>>(W_embed);
    k_embed<<<dim3(8, 8), 256>>>(X, mask_coarse);
    k_init_out<<<512, 256>>>(y, b_out);
    k_zero<<<2048, 256>>>();
    k_scan<<<128, 512, SMEM_FLOATS * 4>>>(mask_fine, W_deconv, w1, w2, w_out, y);
}

// round 8
// speedup vs baseline: 1.0188x; 1.0188x over previous
#include <cuda_runtime.h>
#include <math.h>

// ---------------- problem dims ----------------
#define T_STEPS   128
#define IN_DIM    512
#define C_INT     8
#define ISQ       16
#define DIMN      256
#define NCH       8
#define OUT_CH    16
#define EMB_OUT   2048          // C_INT*ISQ*ISQ

// ---------------- scratch (static device globals; no allocs) ----------------
__device__ float g_WT[IN_DIM * EMB_OUT];                 // W_embed transposed
__device__ float g_v[T_STEPS * EMB_OUT];                 // masked coarse activations
__device__ float g_u[T_STEPS][NCH][DIMN * DIMN];         // precomputed deconv input (128MB)
__device__ float g_Zall[T_STEPS + 1][NCH][DIMN * DIMN];  // all states (258MB)
__device__ int   g_flag[256 * 32];                       // per-block step flags

// ---------------- packed fp32 pair FMA (sm_100+) ----------------
__device__ __forceinline__ float2 fma2(float2 d, float2 a, float2 b) {
    unsigned long long ud = *(unsigned long long*)&d;
    unsigned long long ua = *(unsigned long long*)&a;
    unsigned long long ub = *(unsigned long long*)&b;
    asm("fma.rn.f32x2 %0, %1, %2, %0;" : "+l"(ud) : "l"(ua), "l"(ub));
    return *(float2*)&ud;
}

// ---------------- fast tanh: 1 - 2/(e^{2x}+1) ----------------
__device__ __forceinline__ float ftanh(float s) {
    float e = __expf(s + s);
    return 1.f - __fdividef(2.f, e + 1.f);
}

// ---------------- W_embed transpose ----------------
__global__ void k_transpose(const float* __restrict__ W) {
    __shared__ float tile[32][33];
    int ob = blockIdx.x * 32;
    int kb = blockIdx.y * 32;
    int tx = threadIdx.x, ty = threadIdx.y;
#pragma unroll
    for (int i = 0; i < 4; i++)
        tile[ty + 8 * i][tx] = W[(ob + ty + 8 * i) * IN_DIM + kb + tx];
    __syncthreads();
#pragma unroll
    for (int i = 0; i < 4; i++)
        g_WT[(kb + ty + 8 * i) * EMB_OUT + ob + tx] = tile[tx][ty + 8 * i];
}

// ---------------- embed GEMM: v[t][o] = (X[t,:]·W[o,:]) * mask_coarse ------
__global__ __launch_bounds__(256) void k_embed(const float* __restrict__ X,
                                               const float* __restrict__ maskc) {
    __shared__ float sX[16 * IN_DIM];
    int tt0 = blockIdx.x * 16;
    int ob  = blockIdx.y * 256;
    for (int idx = threadIdx.x; idx < 16 * IN_DIM; idx += 256)
        sX[idx] = X[(tt0 + (idx >> 9)) * IN_DIM + (idx & 511)];
    __syncthreads();

    int to = threadIdx.x & 63;
    int tg = threadIdx.x >> 6;
    float acc[4][4];
#pragma unroll
    for (int a = 0; a < 4; a++)
#pragma unroll
        for (int b = 0; b < 4; b++) acc[a][b] = 0.f;

    for (int k = 0; k < IN_DIM; k++) {
        float w[4];
#pragma unroll
        for (int oi = 0; oi < 4; oi++)
            w[oi] = g_WT[k * EMB_OUT + ob + to + 64 * oi];
#pragma unroll
        for (int ti = 0; ti < 4; ti++) {
            float xv = sX[(tg * 4 + ti) * IN_DIM + k];
#pragma unroll
            for (int oi = 0; oi < 4; oi++) acc[ti][oi] += xv * w[oi];
        }
    }
#pragma unroll
    for (int ti = 0; ti < 4; ti++)
#pragma unroll
        for (int oi = 0; oi < 4; oi++) {
            int t = tt0 + tg * 4 + ti;
            int o = ob + to + 64 * oi;
            g_v[t * EMB_OUT + o] = acc[ti][oi] * maskc[o & 255];
        }
}

// ---------------- precompute u = mask_fine * deconv(v) ----------------
// grid (t, c, i): block computes u[t][c][i*16+a][*] for a=0..15
__global__ __launch_bounds__(256) void k_udeconv(const float* __restrict__ Wd,
                                                 const float* __restrict__ maskf) {
    int t = blockIdx.x, c = blockIdx.y, i = blockIdx.z;
    __shared__ float s_v[128];      // [ci][j]
    __shared__ float s_wd[2048];    // [ci][a*16+b]
    int tid = threadIdx.x;
    if (tid < 128) {
        int ci = tid >> 4, j = tid & 15;
        s_v[tid] = g_v[t * EMB_OUT + ci * 256 + i * 16 + j];
    }
    for (int idx = tid; idx < 2048; idx += 256)
        s_wd[idx] = Wd[(idx >> 8) * 2048 + c * 256 + (idx & 255)];
    __syncthreads();

    int j = tid >> 4, b = tid & 15;
    float vv[8];
#pragma unroll
    for (int ci = 0; ci < 8; ci++) vv[ci] = s_v[ci * 16 + j];
#pragma unroll
    for (int a = 0; a < 16; a++) {
        float s = 0.f;
#pragma unroll
        for (int ci = 0; ci < 8; ci++) s += vv[ci] * s_wd[ci * 256 + a * 16 + b];
        int row = i * 16 + a;
        g_u[t][c][row * 256 + tid] = s * maskf[row * 256 + tid];
    }
}

// ---------------- init output with bias ----------------
__global__ void k_init_out(float* __restrict__ y, const float* __restrict__ b) {
    int idx = blockIdx.x * 256 + threadIdx.x;
    if (idx < T_STEPS * 1024) y[idx] = b[(idx >> 6) & 15];
}

// ---------------- zero initial state + flags ----------------
__global__ void k_zero() {
    int idx = blockIdx.x * 256 + threadIdx.x;
    if (idx < 256 * 32) g_flag[idx] = 0;
    if (idx < NCH * DIMN * DIMN) g_Zall[0][0][idx] = 0.f;
}

// ---------------- conv tap macro (rr = compile-time after unroll) ----------
#define CONV_RR(rr) do {                                                       \
    float t0 = s_tile[rr][sc - 4], t1 = s_tile[rr][sc - 2],                    \
          t2 = s_tile[rr][sc],     t3 = s_tile[rr][sc + 2],                    \
          t4 = s_tile[rr][sc + 4];                                             \
    _Pragma("unroll")                                                          \
    for (int a = 0; a < 5; a++) { int r = (rr) - 2 * a;                        \
        if (r >= 0 && r < 8)                                                   \
            acc[r] += t0 * w2[a*5+0] + t1 * w2[a*5+1] + t2 * w2[a*5+2]         \
                    + t3 * w2[a*5+3] + t4 * w2[a*5+4]; }                       \
    if ((rr) >= 3 && (rr) <= 12) {                                             \
        float u0 = s_tile[rr][sc - 1], u2 = s_tile[rr][sc + 1];                \
        _Pragma("unroll")                                                      \
        for (int a = 0; a < 3; a++) { int r = (rr) - 3 - a;                    \
            if (r >= 0 && r < 8)                                               \
                acc[r] += u0 * w1[a*3+0] + t2 * w1[a*3+1] + u2 * w1[a*3+2]; }  \
    }                                                                          \
} while (0)

// ---------------- persistent reservoir scan (no readout) ----------------
// 256 blocks (occ 2): block -> (c = b>>5, rows r0..r0+7); thread = column x
__global__ __launch_bounds__(256, 2) void k_scan(const float* __restrict__ w1g,
                                                 const float* __restrict__ w2g)
{
    const int blk = blockIdx.x;
    const int c   = blk >> 5;
    const int bb_ = blk & 31;
    const int r0  = bb_ << 3;
    const int tid = threadIdx.x;
    const int x   = tid;
    const int prev = (c << 5) | ((bb_ + 31) & 31);
    const int next = (c << 5) | ((bb_ + 1) & 31);

    __shared__ __align__(16) float s_tile[16][264];

    for (int idx = tid; idx < 16 * 264; idx += 256)
        ((float*)s_tile)[idx] = 0.f;
    float w1[9], w2[25];
#pragma unroll
    for (int i = 0; i < 9; i++)  w1[i] = 0.9f * w1g[c * 9 + i];
#pragma unroll
    for (int i = 0; i < 25; i++) w2[i] = 0.1f * w2g[c * 25 + i];
    const int sc = x + 4;
    __syncthreads();

    for (int t = 0; t < T_STEPS; t++) {
        // early input prefetch (independent of neighbors)
        float ur[8];
#pragma unroll
        for (int r = 0; r < 8; r++)
            ur[r] = __ldcg(&g_u[t][c][(r0 + r) * 256 + x]);

        // interior conv first: tile rows 4..11 (our own z, no wait needed)
        float acc[8];
#pragma unroll
        for (int r = 0; r < 8; r++) acc[r] = 0.f;
#pragma unroll
        for (int rr = 4; rr < 12; rr++) CONV_RR(rr);

        if (t > 0) {
            if (tid < 2) {
                volatile int* f = &g_flag[(tid == 0 ? prev : next) * 32];
                while (*f < t) { }
                __threadfence();
            }
            __syncthreads();
            const float* __restrict__ Zc = &g_Zall[t][c][0];
            for (int idx = tid; idx < 8 * 264; idx += 256) {
                int rr = idx / 264, sc2 = idx - rr * 264;
                int tr = rr < 4 ? rr : rr + 8;         // tile rows 0..3, 12..15
                int gr = (r0 - 4 + tr) & 255;
                int gc = (sc2 - 4) & 255;
                s_tile[tr][sc2] = __ldcg(&Zc[gr * 256 + gc]);
            }
            __syncthreads();
        } else {
            __syncthreads();   // order interior reads vs epilogue z writes
        }

        // halo conv: tile rows 0..3, 12..15
#pragma unroll
        for (int rr = 0; rr < 4; rr++) CONV_RR(rr);
#pragma unroll
        for (int rr = 12; rr < 16; rr++) CONV_RR(rr);

        // epilogue: tanh, retain in smem, publish state
        float* __restrict__ Zn = &g_Zall[t + 1][c][0];
#pragma unroll
        for (int r = 0; r < 8; r++) {
            float z = ftanh(acc[r] + ur[r]);
            s_tile[4 + r][sc] = z;
            if (x < 4)    s_tile[4 + r][x + 260] = z;
            if (x >= 252) s_tile[4 + r][x - 252] = z;
            __stcg(&Zn[(r0 + r) * 256 + x], z);
        }

        __syncthreads();
        if (t < T_STEPS - 1 && tid == 0) {
            __threadfence();
            *(volatile int*)&g_flag[blk * 32] = t + 1;
        }
    }
}

// ---------------- batched readout: y += sum_c sum_ab z*w ----------------
// block (t, c); 256 threads: iy = tid>>5, b = tid&31.
// Thread accumulates (8 jw x 16 oc) outputs for its (iy, b) via f32x2 pairs.
__global__ __launch_bounds__(256) void k_readout(const float* __restrict__ wog,
                                                 float* __restrict__ yout)
{
    const int t = blockIdx.x, c = blockIdx.y;
    extern __shared__ __align__(16) float sm[];
    float* s_w = sm;                 // [(a*32+b)*18 + oc], 18432 floats
    float* s_z = sm + 1024 * 18;     // [32 rows][256 cols], 8192 floats

    const int tid = threadIdx.x;
    const int iy = tid >> 5, b = tid & 31;

    for (int idx = tid; idx < 16384; idx += 256) {
        int oc = idx >> 10, ab = idx & 1023;
        s_w[ab * 18 + oc] = wog[oc * 8192 + c * 1024 + ab];
    }

    float2 accP[64];
#pragma unroll
    for (int i = 0; i < 64; i++) accP[i] = make_float2(0.f, 0.f);

    const float* __restrict__ Zs = &g_Zall[t + 1][c][0];

    for (int k = 0; k < 8; k++) {       // chunk over a in groups of 4
        __syncthreads();
        for (int idx = tid; idx < 8192; idx += 256) {
            int rl = idx >> 8, col = idx & 255;
            int grow = (rl >> 2) * 32 + k * 4 + (rl & 3);
            s_z[rl * 256 + col] = __ldcg(&Zs[grow * 256 + col]);
        }
        __syncthreads();
#pragma unroll
        for (int da = 0; da < 4; da++) {
            int a  = k * 4 + da;
            int rl = iy * 4 + da;
            float zv[8];
#pragma unroll
            for (int jw = 0; jw < 8; jw++) zv[jw] = s_z[rl * 256 + jw * 32 + b];
            const float* wrow = &s_w[(a * 32 + b) * 18];
            float2 wP[8];
#pragma unroll
            for (int p = 0; p < 8; p++) wP[p] = *(const float2*)&wrow[2 * p];
#pragma unroll
            for (int jw = 0; jw < 8; jw++) {
                float2 zp = make_float2(zv[jw], zv[jw]);
#pragma unroll
                for (int p = 0; p < 8; p++)
                    accP[jw * 8 + p] = fma2(accP[jw * 8 + p], zp, wP[p]);
            }
        }
    }

    // butterfly reduce over b (all lanes end with full sums)
#pragma unroll
    for (int i = 0; i < 64; i++) {
#pragma unroll
        for (int d = 16; d >= 1; d >>= 1) {
            accP[i].x += __shfl_xor_sync(0xffffffffu, accP[i].x, d);
            accP[i].y += __shfl_xor_sync(0xffffffffu, accP[i].y, d);
        }
    }
    // lane b commits outputs i = 2b, 2b+1 (static indices, predicated)
#pragma unroll
    for (int i = 0; i < 64; i++) {
        if ((i >> 1) == b) {
            int jw = i >> 3, p = i & 7;
            atomicAdd(&yout[t * 1024 + (2 * p) * 64 + iy * 8 + jw], accP[i].x);
            atomicAdd(&yout[t * 1024 + (2 * p + 1) * 64 + iy * 8 + jw], accP[i].y);
        }
    }
}

#define RO_SMEM ((1024 * 18 + 32 * 256) * 4)

// ---------------- launcher (graph-capturable, alloc-free) ----------------
extern "C" void kernel_launch(void* const* d_in, const int* in_sizes, int n_in,
                              void* d_out, int out_size)
{
    const float* X           = (const float*)d_in[0];  // [128,512]
    const float* W_embed     = (const float*)d_in[1];  // [2048,512]
    const float* mask_coarse = (const float*)d_in[2];  // [16,16]
    const float* mask_fine   = (const float*)d_in[3];  // [256,256]
    const float* W_deconv    = (const float*)d_in[4];  // [8,8,16,16]
    const float* w1          = (const float*)d_in[5];  // [8,1,3,3]
    const float* w2          = (const float*)d_in[6];  // [8,1,5,5]
    const float* w_out       = (const float*)d_in[7];  // [16,8,32,32]
    const float* b_out       = (const float*)d_in[8];  // [16]
    float* y = (float*)d_out;                          // [128,1024]

    cudaFuncSetAttribute(k_readout, cudaFuncAttributeMaxDynamicSharedMemorySize,
                         RO_SMEM);

    k_transpose<<<dim3(64, 16), dim3(32, 8)>>>(W_embed);
    k_embed<<<dim3(8, 8), 256>>>(X, mask_coarse);
    k_udeconv<<<dim3(T_STEPS, NCH, 16), 256>>>(W_deconv, mask_fine);
    k_init_out<<<512, 256>>>(y, b_out);
    k_zero<<<8192, 256>>>();
    k_scan<<<256, 256>>>(w1, w2);
    k_readout<<<dim3(T_STEPS, NCH), 256, RO_SMEM>>>(w_out, y);
}

// round 9
// speedup vs baseline: 1.1203x; 1.0997x over previous
#include <cuda_runtime.h>
#include <math.h>

// ---------------- problem dims ----------------
#define T_STEPS   128
#define IN_DIM    512
#define C_INT     8
#define ISQ       16
#define DIMN      256
#define NCH       8
#define OUT_CH    16
#define EMB_OUT   2048          // C_INT*ISQ*ISQ

// ---------------- scratch (static device globals; no allocs) ----------------
__device__ float g_WT[IN_DIM * EMB_OUT];                 // W_embed transposed
__device__ float g_v[T_STEPS * EMB_OUT];                 // masked coarse activations
__device__ float g_u[T_STEPS][NCH][DIMN * DIMN];         // precomputed deconv input
__device__ float g_Zall[T_STEPS + 1][NCH][DIMN * DIMN];  // all states
__device__ int   g_flag[256 * 32];                       // per-block step flags

// ---------------- packed fp32 pair FMA (sm_100+) ----------------
__device__ __forceinline__ float2 fma2(float2 d, float2 a, float2 b) {
    unsigned long long ud = *(unsigned long long*)&d;
    unsigned long long ua = *(unsigned long long*)&a;
    unsigned long long ub = *(unsigned long long*)&b;
    asm("fma.rn.f32x2 %0, %1, %2, %0;" : "+l"(ud) : "l"(ua), "l"(ub));
    return *(float2*)&ud;
}

__device__ __forceinline__ int ld_acq(const int* p) {
    int v;
    asm volatile("ld.global.acquire.gpu.b32 %0, [%1];" : "=r"(v) : "l"(p));
    return v;
}

// ---------------- fast tanh: 1 - 2/(e^{2x}+1) ----------------
__device__ __forceinline__ float ftanh(float s) {
    float e = __expf(s + s);
    return 1.f - __fdividef(2.f, e + 1.f);
}

// ---------------- W_embed transpose ----------------
__global__ void k_transpose(const float* __restrict__ W) {
    __shared__ float tile[32][33];
    int ob = blockIdx.x * 32;
    int kb = blockIdx.y * 32;
    int tx = threadIdx.x, ty = threadIdx.y;
#pragma unroll
    for (int i = 0; i < 4; i++)
        tile[ty + 8 * i][tx] = W[(ob + ty + 8 * i) * IN_DIM + kb + tx];
    __syncthreads();
#pragma unroll
    for (int i = 0; i < 4; i++)
        g_WT[(kb + ty + 8 * i) * EMB_OUT + ob + tx] = tile[tx][ty + 8 * i];
}

// ---------------- embed GEMM: v[t][o] = (X[t,:]·W[o,:]) * mask_coarse ------
__global__ __launch_bounds__(256) void k_embed(const float* __restrict__ X,
                                               const float* __restrict__ maskc) {
    __shared__ float sX[16 * IN_DIM];
    int tt0 = blockIdx.x * 16;
    int ob  = blockIdx.y * 256;
    for (int idx = threadIdx.x; idx < 16 * IN_DIM; idx += 256)
        sX[idx] = X[(tt0 + (idx >> 9)) * IN_DIM + (idx & 511)];
    __syncthreads();

    int to = threadIdx.x & 63;
    int tg = threadIdx.x >> 6;
    float acc[4][4];
#pragma unroll
    for (int a = 0; a < 4; a++)
#pragma unroll
        for (int b = 0; b < 4; b++) acc[a][b] = 0.f;

    for (int k = 0; k < IN_DIM; k++) {
        float w[4];
#pragma unroll
        for (int oi = 0; oi < 4; oi++)
            w[oi] = g_WT[k * EMB_OUT + ob + to + 64 * oi];
#pragma unroll
        for (int ti = 0; ti < 4; ti++) {
            float xv = sX[(tg * 4 + ti) * IN_DIM + k];
#pragma unroll
            for (int oi = 0; oi < 4; oi++) acc[ti][oi] += xv * w[oi];
        }
    }
#pragma unroll
    for (int ti = 0; ti < 4; ti++)
#pragma unroll
        for (int oi = 0; oi < 4; oi++) {
            int t = tt0 + tg * 4 + ti;
            int o = ob + to + 64 * oi;
            g_v[t * EMB_OUT + o] = acc[ti][oi] * maskc[o & 255];
        }
}

// ---------------- precompute u = mask_fine * deconv(v) ----------------
__global__ __launch_bounds__(256) void k_udeconv(const float* __restrict__ Wd,
                                                 const float* __restrict__ maskf) {
    int t = blockIdx.x, c = blockIdx.y, i = blockIdx.z;
    __shared__ float s_v[128];
    __shared__ float s_wd[2048];
    int tid = threadIdx.x;
    if (tid < 128) {
        int ci = tid >> 4, j = tid & 15;
        s_v[tid] = g_v[t * EMB_OUT + ci * 256 + i * 16 + j];
    }
    for (int idx = tid; idx < 2048; idx += 256)
        s_wd[idx] = Wd[(idx >> 8) * 2048 + c * 256 + (idx & 255)];
    __syncthreads();

    int j = tid >> 4;
    float vv[8];
#pragma unroll
    for (int ci = 0; ci < 8; ci++) vv[ci] = s_v[ci * 16 + j];
#pragma unroll
    for (int a = 0; a < 16; a++) {
        float s = 0.f;
#pragma unroll
        for (int ci = 0; ci < 8; ci++)
            s += vv[ci] * s_wd[ci * 256 + a * 16 + (tid & 15)];
        int row = i * 16 + a;
        g_u[t][c][row * 256 + tid] = s * maskf[row * 256 + tid];
    }
}

// ---------------- init output with bias ----------------
__global__ void k_init_out(float* __restrict__ y, const float* __restrict__ b) {
    int idx = blockIdx.x * 256 + threadIdx.x;
    if (idx < T_STEPS * 1024) y[idx] = b[(idx >> 6) & 15];
}

// ---------------- zero initial state + flags ----------------
__global__ void k_zero() {
    int idx = blockIdx.x * 256 + threadIdx.x;
    if (idx < 256 * 32) g_flag[idx] = 0;
    if (idx < NCH * DIMN * DIMN) g_Zall[0][0][idx] = 0.f;
}

// acc half accessor (r is compile-time)
#define ACCH(r) ((r) & 1 ? A[(r) >> 1].y : A[(r) >> 1].x)

// w2 pair-row contribution: tile pair s2, cols sc+{-4,-2,0,2,4}
#define W2_S2(s2) do {                                                        \
    const float2* row_ = s_tile2[s2];                                         \
    float2 T0 = row_[sc - 4], T1 = row_[sc - 2], T2 = row_[sc],               \
           T3 = row_[sc + 2], T4 = row_[sc + 4];                              \
    _Pragma("unroll")                                                         \
    for (int a = 0; a < 5; a++) {                                             \
        int p = (s2) - a;                                                     \
        if (p >= 0 && p < 4) {                                                \
            A[p] = fma2(A[p], T0, w2p[a * 5 + 0]);                            \
            A[p] = fma2(A[p], T1, w2p[a * 5 + 1]);                            \
            A[p] = fma2(A[p], T2, w2p[a * 5 + 2]);                            \
            A[p] = fma2(A[p], T3, w2p[a * 5 + 3]);                            \
            A[p] = fma2(A[p], T4, w2p[a * 5 + 4]);                            \
        }                                                                     \
    }                                                                         \
} while (0)

// w1 contribution from tile pair kk (rows 2kk, 2kk+1), cols sc+{-1,0,1}
#define W1_K(kk) do {                                                         \
    const float2* row_ = s_tile2[kk];                                         \
    float2 Lv = row_[sc - 1], Cv = row_[sc], Rv = row_[sc + 1];               \
    _Pragma("unroll")                                                         \
    for (int h = 0; h < 2; h++) {                                             \
        float lv = h ? Lv.y : Lv.x, cv = h ? Cv.y : Cv.x,                     \
              rv = h ? Rv.y : Rv.x;                                           \
        int m = 2 * (kk) + h;                                                 \
        _Pragma("unroll")                                                     \
        for (int ap = 0; ap < 3; ap++) {                                      \
            int r = m - 3 - ap;                                               \
            if (r >= 0 && r < 8)                                              \
                ACCH(r) += lv * w1[ap * 3 + 0] + cv * w1[ap * 3 + 1]          \
                         + rv * w1[ap * 3 + 2];                               \
        }                                                                     \
    }                                                                         \
} while (0)

// ---------------- persistent reservoir scan ----------------
// 256 blocks (occ 2): block -> (c = b>>5, rows r0..r0+7); thread = column x.
// State tile as vertical float2 row-pairs; f32x2 conv; neighbor flag sync.
__global__ __launch_bounds__(256, 2) void k_scan(const float* __restrict__ w1g,
                                                 const float* __restrict__ w2g)
{
    const int blk = blockIdx.x;
    const int c   = blk >> 5;
    const int bb_ = blk & 31;
    const int r0  = bb_ << 3;
    const int tid = threadIdx.x;
    const int x   = tid;
    const int prev = (c << 5) | ((bb_ + 31) & 31);
    const int next = (c << 5) | ((bb_ + 1) & 31);

    // pairs 0..7 cover tile rows 0..15 = global rows r0-4 .. r0+11
    __shared__ __align__(16) float2 s_tile2[8][264];

    for (int idx = tid; idx < 8 * 264; idx += 256)
        ((float2*)s_tile2)[idx] = make_float2(0.f, 0.f);

    float  w1[9];
    float2 w2p[25];
#pragma unroll
    for (int i = 0; i < 9; i++)  w1[i] = 0.9f * w1g[c * 9 + i];
#pragma unroll
    for (int i = 0; i < 25; i++) {
        float w = 0.1f * w2g[c * 25 + i];
        w2p[i] = make_float2(w, w);
    }
    const int sc = x + 4;

    // staging geometry (constant per thread)
    const int Pl  = tid >> 6;                    // 0..3
    const int prS = Pl < 2 ? Pl : Pl + 4;        // pair 0,1,6,7
    const int gA  = (r0 - 4 + 2 * prS) & 255;    // even global row
    const int cq  = (tid & 63) * 4;

    __syncthreads();

    for (int t = 0; t < T_STEPS; t++) {
        const float* __restrict__ Zc = &g_Zall[t][c][0];
        float* __restrict__       Zn = &g_Zall[t + 1][c][0];

        // early input prefetch
        float ur[8];
#pragma unroll
        for (int r = 0; r < 8; r++)
            ur[r] = __ldcg(&g_u[t][c][(r0 + r) * 256 + x]);

        // interior conv (own rows, pairs 2..5) before any waiting
        float2 A[4];
#pragma unroll
        for (int p = 0; p < 4; p++) A[p] = make_float2(0.f, 0.f);
        W2_S2(2); W2_S2(3); W2_S2(4); W2_S2(5);
        W1_K(2);  W1_K(3);  W1_K(4);  W1_K(5);

        if (t > 0) {
            // acquire-poll both neighbor flags (all threads; 1 L2 line each)
            while (ld_acq(&g_flag[prev * 32]) < t) { }
            while (ld_acq(&g_flag[next * 32]) < t) { }

            // stage halo pairs 0,1,6,7: center cols vectorized
            float4 a4 = __ldcg((const float4*)&Zc[gA * 256 + cq]);
            float4 b4 = __ldcg((const float4*)&Zc[(gA + 1) * 256 + cq]);
            float4* dst = (float4*)&s_tile2[prS][4 + cq];
            dst[0] = make_float4(a4.x, b4.x, a4.y, b4.y);
            dst[1] = make_float4(a4.z, b4.z, a4.w, b4.w);
            // edge cols: smem cols 0..3 (global 252..255), 260..263 (global 0..3)
            if (tid < 32) {
                int P2  = tid >> 3;
                int pr2 = P2 < 2 ? P2 : P2 + 4;
                int e   = tid & 7;
                int sc2 = e < 4 ? e : e + 256;
                int gc  = (sc2 - 4) & 255;
                int g2  = (r0 - 4 + 2 * pr2) & 255;
                s_tile2[pr2][sc2] = make_float2(__ldcg(&Zc[g2 * 256 + gc]),
                                                __ldcg(&Zc[(g2 + 1) * 256 + gc]));
            }
        }
        __syncthreads();   // staging visible; prior epilogue reads protected

        // halo conv: pairs 0,1,6,7 (w2) and 1,6 (w1)
        W2_S2(0); W2_S2(1); W2_S2(6); W2_S2(7);
        W1_K(1);  W1_K(6);

        // epilogue: tanh, retain own rows (pairs 2..5), publish state
        float z[8];
#pragma unroll
        for (int r = 0; r < 8; r++) {
            z[r] = ftanh(ACCH(r) + ur[r]);
            __stcg(&Zn[(r0 + r) * 256 + x], z[r]);
        }
#pragma unroll
        for (int q = 0; q < 4; q++) {
            float2 zz = make_float2(z[2 * q], z[2 * q + 1]);
            s_tile2[2 + q][sc] = zz;
            if (x < 4)    s_tile2[2 + q][x + 260] = zz;
            if (x >= 252) s_tile2[2 + q][x - 252] = zz;
        }

        __syncthreads();   // all reads of old halo + all writes complete

        if (t < T_STEPS - 1 && tid == 0) {
            __threadfence();
            *(volatile int*)&g_flag[blk * 32] = t + 1;
        }
    }
}

// ---------------- batched readout: y += sum_c sum_ab z*w ----------------
__global__ __launch_bounds__(256) void k_readout(const float* __restrict__ wog,
                                                 float* __restrict__ yout)
{
    const int t = blockIdx.x, c = blockIdx.y;
    extern __shared__ __align__(16) float sm[];
    float* s_w = sm;                 // [(a*32+b)*18 + oc]
    float* s_z = sm + 1024 * 18;     // [32 rows][256 cols]

    const int tid = threadIdx.x;
    const int iy = tid >> 5, b = tid & 31;

    for (int idx = tid; idx < 16384; idx += 256) {
        int oc = idx >> 10, ab = idx & 1023;
        s_w[ab * 18 + oc] = wog[oc * 8192 + c * 1024 + ab];
    }

    float2 accP[64];
#pragma unroll
    for (int i = 0; i < 64; i++) accP[i] = make_float2(0.f, 0.f);

    const float* __restrict__ Zs = &g_Zall[t + 1][c][0];

    for (int k = 0; k < 8; k++) {
        __syncthreads();
        for (int idx = tid; idx < 8192; idx += 256) {
            int rl = idx >> 8, col = idx & 255;
            int grow = (rl >> 2) * 32 + k * 4 + (rl & 3);
            s_z[rl * 256 + col] = __ldcg(&Zs[grow * 256 + col]);
        }
        __syncthreads();
#pragma unroll
        for (int da = 0; da < 4; da++) {
            int a  = k * 4 + da;
            int rl = iy * 4 + da;
            float zv[8];
#pragma unroll
            for (int jw = 0; jw < 8; jw++) zv[jw] = s_z[rl * 256 + jw * 32 + b];
            const float* wrow = &s_w[(a * 32 + b) * 18];
            float2 wP[8];
#pragma unroll
            for (int p = 0; p < 8; p++) wP[p] = *(const float2*)&wrow[2 * p];
#pragma unroll
            for (int jw = 0; jw < 8; jw++) {
                float2 zp = make_float2(zv[jw], zv[jw]);
#pragma unroll
                for (int p = 0; p < 8; p++)
                    accP[jw * 8 + p] = fma2(accP[jw * 8 + p], zp, wP[p]);
            }
        }
    }

#pragma unroll
    for (int i = 0; i < 64; i++) {
#pragma unroll
        for (int d = 16; d >= 1; d >>= 1) {
            accP[i].x += __shfl_xor_sync(0xffffffffu, accP[i].x, d);
            accP[i].y += __shfl_xor_sync(0xffffffffu, accP[i].y, d);
        }
    }
#pragma unroll
    for (int i = 0; i < 64; i++) {
        if ((i >> 1) == b) {
            int jw = i >> 3, p = i & 7;
            atomicAdd(&yout[t * 1024 + (2 * p) * 64 + iy * 8 + jw], accP[i].x);
            atomicAdd(&yout[t * 1024 + (2 * p + 1) * 64 + iy * 8 + jw], accP[i].y);
        }
    }
}

#define RO_SMEM ((1024 * 18 + 32 * 256) * 4)

// ---------------- launcher (graph-capturable, alloc-free) ----------------
extern "C" void kernel_launch(void* const* d_in, const int* in_sizes, int n_in,
                              void* d_out, int out_size)
{
    const float* X           = (const float*)d_in[0];  // [128,512]
    const float* W_embed     = (const float*)d_in[1];  // [2048,512]
    const float* mask_coarse = (const float*)d_in[2];  // [16,16]
    const float* mask_fine   = (const float*)d_in[3];  // [256,256]
    const float* W_deconv    = (const float*)d_in[4];  // [8,8,16,16]
    const float* w1          = (const float*)d_in[5];  // [8,1,3,3]
    const float* w2          = (const float*)d_in[6];  // [8,1,5,5]
    const float* w_out       = (const float*)d_in[7];  // [16,8,32,32]
    const float* b_out       = (const float*)d_in[8];  // [16]
    float* y = (float*)d_out;                          // [128,1024]

    cudaFuncSetAttribute(k_readout, cudaFuncAttributeMaxDynamicSharedMemorySize,
                         RO_SMEM);

    k_transpose<<<dim3(64, 16), dim3(32, 8)>>>(W_embed);
    k_embed<<<dim3(8, 8), 256>>>(X, mask_coarse);
    k_udeconv<<<dim3(T_STEPS, NCH, 16), 256>>>(W_deconv, mask_fine);
    k_init_out<<<512, 256>>>(y, b_out);
    k_zero<<<2048, 256>>>();
    k_scan<<<256, 256>>>(w1, w2);
    k_readout<<<dim3(T_STEPS, NCH), 256, RO_SMEM>>>(w_out, y);
}

// round 11
// speedup vs baseline: 1.1304x; 1.0090x over previous
#include <cuda_runtime.h>
#include <math.h>

// ---------------- problem dims ----------------
#define T_STEPS   128
#define IN_DIM    512
#define C_INT     8
#define ISQ       16
#define DIMN      256
#define NCH       8
#define OUT_CH    16
#define EMB_OUT   2048          // C_INT*ISQ*ISQ
#define N_ROUNDS  (T_STEPS / 2)

// ---------------- scratch (static device globals; no allocs) ----------------
__device__ float g_WT[IN_DIM * EMB_OUT];                 // W_embed transposed
__device__ float g_v[T_STEPS * EMB_OUT];                 // masked coarse activations
__device__ float g_u[T_STEPS][NCH][DIMN * DIMN];         // precomputed deconv input
__device__ float g_Zall[T_STEPS + 1][NCH][DIMN * DIMN];  // all states (for readout)
__device__ float g_halo[2][256][8][DIMN];                // parity-buffered own rows (4MB)
__device__ int   g_flag[256 * 32];                       // per-block round flags

// ---------------- packed fp32 pair FMA (sm_100+) ----------------
__device__ __forceinline__ float2 fma2(float2 d, float2 a, float2 b) {
    unsigned long long ud = *(unsigned long long*)&d;
    unsigned long long ua = *(unsigned long long*)&a;
    unsigned long long ub = *(unsigned long long*)&b;
    asm("fma.rn.f32x2 %0, %1, %2, %0;" : "+l"(ud) : "l"(ua), "l"(ub));
    return *(float2*)&ud;
}

__device__ __forceinline__ int ld_acq(const int* p) {
    int v;
    asm volatile("ld.global.acquire.gpu.b32 %0, [%1];" : "=r"(v) : "l"(p));
    return v;
}

// ---------------- fast tanh: 1 - 2/(e^{2x}+1) ----------------
__device__ __forceinline__ float ftanh(float s) {
    float e = __expf(s + s);
    return 1.f - __fdividef(2.f, e + 1.f);
}

// ---------------- W_embed transpose ----------------
__global__ void k_transpose(const float* __restrict__ W) {
    __shared__ float tile[32][33];
    int ob = blockIdx.x * 32;
    int kb = blockIdx.y * 32;
    int tx = threadIdx.x, ty = threadIdx.y;
#pragma unroll
    for (int i = 0; i < 4; i++)
        tile[ty + 8 * i][tx] = W[(ob + ty + 8 * i) * IN_DIM + kb + tx];
    __syncthreads();
#pragma unroll
    for (int i = 0; i < 4; i++)
        g_WT[(kb + ty + 8 * i) * EMB_OUT + ob + tx] = tile[tx][ty + 8 * i];
}

// ---------------- embed GEMM: v[t][o] = (X[t,:]·W[o,:]) * mask_coarse ------
__global__ __launch_bounds__(256) void k_embed(const float* __restrict__ X,
                                               const float* __restrict__ maskc) {
    __shared__ float sX[16 * IN_DIM];
    int tt0 = blockIdx.x * 16;
    int ob  = blockIdx.y * 256;
    for (int idx = threadIdx.x; idx < 16 * IN_DIM; idx += 256)
        sX[idx] = X[(tt0 + (idx >> 9)) * IN_DIM + (idx & 511)];
    __syncthreads();

    int to = threadIdx.x & 63;
    int tg = threadIdx.x >> 6;
    float acc[4][4];
#pragma unroll
    for (int a = 0; a < 4; a++)
#pragma unroll
        for (int b = 0; b < 4; b++) acc[a][b] = 0.f;

    for (int k = 0; k < IN_DIM; k++) {
        float w[4];
#pragma unroll
        for (int oi = 0; oi < 4; oi++)
            w[oi] = g_WT[k * EMB_OUT + ob + to + 64 * oi];
#pragma unroll
        for (int ti = 0; ti < 4; ti++) {
            float xv = sX[(tg * 4 + ti) * IN_DIM + k];
#pragma unroll
            for (int oi = 0; oi < 4; oi++) acc[ti][oi] += xv * w[oi];
        }
    }
#pragma unroll
    for (int ti = 0; ti < 4; ti++)
#pragma unroll
        for (int oi = 0; oi < 4; oi++) {
            int t = tt0 + tg * 4 + ti;
            int o = ob + to + 64 * oi;
            g_v[t * EMB_OUT + o] = acc[ti][oi] * maskc[o & 255];
        }
}

// ---------------- precompute u = mask_fine * deconv(v) ----------------
__global__ __launch_bounds__(256) void k_udeconv(const float* __restrict__ Wd,
                                                 const float* __restrict__ maskf) {
    int t = blockIdx.x, c = blockIdx.y, i = blockIdx.z;
    __shared__ float s_v[128];
    __shared__ float s_wd[2048];
    int tid = threadIdx.x;
    if (tid < 128) {
        int ci = tid >> 4, j = tid & 15;
        s_v[tid] = g_v[t * EMB_OUT + ci * 256 + i * 16 + j];
    }
    for (int idx = tid; idx < 2048; idx += 256)
        s_wd[idx] = Wd[(idx >> 8) * 2048 + c * 256 + (idx & 255)];
    __syncthreads();

    int j = tid >> 4;
    float vv[8];
#pragma unroll
    for (int ci = 0; ci < 8; ci++) vv[ci] = s_v[ci * 16 + j];
#pragma unroll
    for (int a = 0; a < 16; a++) {
        float s = 0.f;
#pragma unroll
        for (int ci = 0; ci < 8; ci++)
            s += vv[ci] * s_wd[ci * 256 + a * 16 + (tid & 15)];
        int row = i * 16 + a;
        g_u[t][c][row * 256 + tid] = s * maskf[row * 256 + tid];
    }
}

// ---------------- init output with bias ----------------
__global__ void k_init_out(float* __restrict__ y, const float* __restrict__ b) {
    int idx = blockIdx.x * 256 + threadIdx.x;
    if (idx < T_STEPS * 1024) y[idx] = b[(idx >> 6) & 15];
}

// ---------------- zero initial state + flags ----------------
__global__ void k_zero() {
    int idx = blockIdx.x * 256 + threadIdx.x;
    if (idx < 256 * 32) g_flag[idx] = 0;
    if (idx < NCH * DIMN * DIMN) g_Zall[0][0][idx] = 0.f;
}

// acc half accessors (q compile-time)
#define ACCA(q) ((q) & 1 ? AA[(q) >> 1].y : AA[(q) >> 1].x)
#define ACCB(q) ((q) & 1 ? BB[(q) >> 1].y : BB[(q) >> 1].x)

// Phase A w2: source tile pair s (0..11) -> acc pair P = s - a, P in [0,8)
#define W2A(s) do {                                                           \
    const float2* row_ = s_tile2[s];                                          \
    float2 T0 = row_[sc - 4], T1 = row_[sc - 2], T2 = row_[sc],               \
           T3 = row_[sc + 2], T4 = row_[sc + 4];                              \
    _Pragma("unroll")                                                         \
    for (int a = 0; a < 5; a++) {                                             \
        int P = (s) - a;                                                      \
        if (P >= 0 && P < 8) {                                                \
            AA[P] = fma2(AA[P], T0, w2p[a * 5 + 0]);                          \
            AA[P] = fma2(AA[P], T1, w2p[a * 5 + 1]);                          \
            AA[P] = fma2(AA[P], T2, w2p[a * 5 + 2]);                          \
            AA[P] = fma2(AA[P], T3, w2p[a * 5 + 3]);                          \
            AA[P] = fma2(AA[P], T4, w2p[a * 5 + 4]);                          \
        }                                                                     \
    }                                                                         \
} while (0)

// Phase B w2: source tile pair s (2..9) -> acc pair P = s - a - 2, P in [0,4)
#define W2B(s) do {                                                           \
    const float2* row_ = s_tile2[s];                                          \
    float2 T0 = row_[sc - 4], T1 = row_[sc - 2], T2 = row_[sc],               \
           T3 = row_[sc + 2], T4 = row_[sc + 4];                              \
    _Pragma("unroll")                                                         \
    for (int a = 0; a < 5; a++) {                                             \
        int P = (s) - a - 2;                                                  \
        if (P >= 0 && P < 4) {                                                \
            BB[P] = fma2(BB[P], T0, w2p[a * 5 + 0]);                          \
            BB[P] = fma2(BB[P], T1, w2p[a * 5 + 1]);                          \
            BB[P] = fma2(BB[P], T2, w2p[a * 5 + 2]);                          \
            BB[P] = fma2(BB[P], T3, w2p[a * 5 + 3]);                          \
            BB[P] = fma2(BB[P], T4, w2p[a * 5 + 4]);                          \
        }                                                                     \
    }                                                                         \
} while (0)

// Phase A w1: source pair kk (1..10); row m = 2kk+h -> acc row q = m-3-a in [0,16)
#define W1A(kk) do {                                                          \
    const float2* row_ = s_tile2[kk];                                         \
    float2 Lv = row_[sc - 1], Cv = row_[sc], Rv = row_[sc + 1];               \
    _Pragma("unroll")                                                         \
    for (int h = 0; h < 2; h++) {                                             \
        float lv = h ? Lv.y : Lv.x, cv = h ? Cv.y : Cv.x,                     \
              rv = h ? Rv.y : Rv.x;                                           \
        int m = 2 * (kk) + h;                                                 \
        _Pragma("unroll")                                                     \
        for (int a = 0; a < 3; a++) {                                         \
            int q = m - 3 - a;                                                \
            if (q >= 0 && q < 16)                                             \
                ACCA(q) += lv * w1[a * 3 + 0] + cv * w1[a * 3 + 1]            \
                         + rv * w1[a * 3 + 2];                                \
        }                                                                     \
    }                                                                         \
} while (0)

// Phase B w1: source pair kk (3..8); row m -> acc row q = m-7-a in [0,8)
#define W1B(kk) do {                                                          \
    const float2* row_ = s_tile2[kk];                                         \
    float2 Lv = row_[sc - 1], Cv = row_[sc], Rv = row_[sc + 1];               \
    _Pragma("unroll")                                                         \
    for (int h = 0; h < 2; h++) {                                             \
        float lv = h ? Lv.y : Lv.x, cv = h ? Cv.y : Cv.x,                     \
              rv = h ? Rv.y : Rv.x;                                           \
        int m = 2 * (kk) + h;                                                 \
        _Pragma("unroll")                                                     \
        for (int a = 0; a < 3; a++) {                                         \
            int q = m - 7 - a;                                                \
            if (q >= 0 && q < 8)                                              \
                ACCB(q) += lv * w1[a * 3 + 0] + cv * w1[a * 3 + 1]            \
                         + rv * w1[a * 3 + 2];                                \
        }                                                                     \
    }                                                                         \
} while (0)

// ---------------- persistent reservoir scan: 2 steps per exchange ----------
// 256 blocks (occ 2): block -> (c = b>>5, rows r0..r0+7); thread = column x.
// Tile = 24 rows (12 float2 pairs): global rows r0-8 .. r0+15.
// Round r: phase A = step 2r on 16 rows (tile pairs 2..9), phase B = step
// 2r+1 on own 8 rows (tile pairs 4..7). One neighbor exchange per round.
// Halo is PARITY DOUBLE-BUFFERED: publish round r to g_halo[r&1]; neighbors
// read it in their round r+1. Next write to that parity is round r+2, gated
// by flag >= r+2 (neighbor finished round r+1, i.e., completed that read).
__global__ __launch_bounds__(256, 2) void k_scan(const float* __restrict__ w1g,
                                                 const float* __restrict__ w2g)
{
    const int blk = blockIdx.x;
    const int c   = blk >> 5;
    const int bb_ = blk & 31;
    const int r0  = bb_ << 3;
    const int tid = threadIdx.x;
    const int x   = tid;
    const int prev = (c << 5) | ((bb_ + 31) & 31);
    const int next = (c << 5) | ((bb_ + 1) & 31);

    __shared__ __align__(16) float2 s_tile2[12][264];   // 25.3 KB

    for (int idx = tid; idx < 12 * 264; idx += 256)
        ((float2*)s_tile2)[idx] = make_float2(0.f, 0.f);

    float  w1[9];
    float2 w2p[25];
#pragma unroll
    for (int i = 0; i < 9; i++)  w1[i] = 0.9f * w1g[c * 9 + i];
#pragma unroll
    for (int i = 0; i < 25; i++) {
        float w = 0.1f * w2g[c * 25 + i];
        w2p[i] = make_float2(w, w);
    }
    const int sc = x + 4;
    __syncthreads();

    for (int r = 0; r < N_ROUNDS; r++) {
        const int tA = 2 * r;
        const int pb = r & 1;          // publish buffer this round
        const int sb = pb ^ 1;         // staging buffer (round r-1 publishes)

        // ---- prefetch u for phase A (16 rows, wrapped) ----
        float uA[16];
#pragma unroll
        for (int q = 0; q < 16; q++) {
            int gr = (r0 - 4 + q) & 255;
            uA[q] = __ldcg(&g_u[tA][c][gr * 256 + x]);
        }

        if (r > 0) {
            // wait for ring neighbors to finish round r-1
            while (ld_acq(&g_flag[prev * 32]) < r) { }
            while (ld_acq(&g_flag[next * 32]) < r) { }

            // stage 16 halo rows from neighbors' parity buffers:
            // prev's 8 own rows -> tile pairs 0..3; next's -> pairs 8..11
#pragma unroll
            for (int task = tid; task < 512; task += 256) {
                int hp = task >> 6;                 // 0..7
                int cg = (task & 63) * 4;
                const float* src = (hp < 4)
                    ? &g_halo[sb][prev][2 * hp][0]
                    : &g_halo[sb][next][2 * (hp - 4)][0];
                float4 a4 = __ldcg((const float4*)(src + cg));
                float4 b4 = __ldcg((const float4*)(src + 256 + cg));
                int tp = hp < 4 ? hp : hp + 4;
                float4* dst = (float4*)&s_tile2[tp][4 + cg];
                dst[0] = make_float4(a4.x, b4.x, a4.y, b4.y);
                dst[1] = make_float4(a4.z, b4.z, a4.w, b4.w);
            }
            // wrap edge cols for staged pairs
            if (tid < 64) {
                int hp = tid >> 3;
                int e  = tid & 7;
                int sc2 = e < 4 ? e : e + 256;
                int gc  = (sc2 - 4) & 255;
                const float* src = (hp < 4)
                    ? &g_halo[sb][prev][2 * hp][0]
                    : &g_halo[sb][next][2 * (hp - 4)][0];
                int tp = hp < 4 ? hp : hp + 4;
                s_tile2[tp][sc2] = make_float2(src[gc], src[256 + gc]);
            }
        }
        __syncthreads();   // staging + prior-round tile writes visible

        // ---- phase A conv: out tile pairs 2..9 (16 rows) ----
        float2 AA[8];
#pragma unroll
        for (int p = 0; p < 8; p++) AA[p] = make_float2(0.f, 0.f);
        W2A(0);  W2A(1);  W2A(2);  W2A(3);  W2A(4);  W2A(5);
        W2A(6);  W2A(7);  W2A(8);  W2A(9);  W2A(10); W2A(11);
        W1A(1);  W1A(2);  W1A(3);  W1A(4);  W1A(5);
        W1A(6);  W1A(7);  W1A(8);  W1A(9);  W1A(10);

        float z1[16];
#pragma unroll
        for (int q = 0; q < 16; q++) z1[q] = ftanh(ACCA(q) + uA[q]);

        __syncthreads();   // all phase-A reads done before tile overwrite

        // write z1 into tile pairs 2..9; publish own 8 rows for readout
#pragma unroll
        for (int Q = 0; Q < 8; Q++) {
            float2 zz = make_float2(z1[2 * Q], z1[2 * Q + 1]);
            s_tile2[2 + Q][sc] = zz;
            if (x < 4)    s_tile2[2 + Q][x + 260] = zz;
            if (x >= 252) s_tile2[2 + Q][x - 252] = zz;
        }
        {
            float* __restrict__ Zn1 = &g_Zall[tA + 1][c][0];
#pragma unroll
            for (int q = 4; q < 12; q++)
                __stcg(&Zn1[(r0 + q - 4) * 256 + x], z1[q]);
        }
        __syncthreads();   // z1 visible before phase B reads

        // prefetch u for phase B (own 8 rows)
        float uB[8];
#pragma unroll
        for (int q = 0; q < 8; q++)
            uB[q] = __ldcg(&g_u[tA + 1][c][(r0 + q) * 256 + x]);

        // ---- phase B conv: out tile pairs 4..7 (own 8 rows) ----
        float2 BB[4];
#pragma unroll
        for (int p = 0; p < 4; p++) BB[p] = make_float2(0.f, 0.f);
        W2B(2); W2B(3); W2B(4); W2B(5); W2B(6); W2B(7); W2B(8); W2B(9);
        W1B(3); W1B(4); W1B(5); W1B(6); W1B(7); W1B(8);

        float z2[8];
#pragma unroll
        for (int q = 0; q < 8; q++) z2[q] = ftanh(ACCB(q) + uB[q]);

        // ---- early release: parity-buffered halo publish, fence, flag ----
#pragma unroll
        for (int q = 0; q < 8; q++)
            __stcg(&g_halo[pb][blk][q][x], z2[q]);
        __syncthreads();   // all halo stores issued (and phase-B reads done)
        if (r < N_ROUNDS - 1 && tid == 0) {
            __threadfence();
            *(volatile int*)&g_flag[blk * 32] = r + 1;
        }

        // off-critical-path: tile retain + bulk state store
#pragma unroll
        for (int Q = 0; Q < 4; Q++) {
            float2 zz = make_float2(z2[2 * Q], z2[2 * Q + 1]);
            s_tile2[4 + Q][sc] = zz;
            if (x < 4)    s_tile2[4 + Q][x + 260] = zz;
            if (x >= 252) s_tile2[4 + Q][x - 252] = zz;
        }
        {
            float* __restrict__ Zn2 = &g_Zall[tA + 2][c][0];
#pragma unroll
            for (int q = 0; q < 8; q++)
                __stcg(&Zn2[(r0 + q) * 256 + x], z2[q]);
        }
        // next round's staging writes pairs 0..3 / 8..11 (disjoint from the
        // retain writes to 4..7); the post-stage __syncthreads orders both
        // before the next phase-A reads.
    }
}

// ---------------- batched readout: y += sum_c sum_ab z*w ----------------
__global__ __launch_bounds__(256) void k_readout(const float* __restrict__ wog,
                                                 float* __restrict__ yout)
{
    const int t = blockIdx.x, c = blockIdx.y;
    extern __shared__ __align__(16) float sm[];
    float* s_w = sm;                 // [(a*32+b)*18 + oc]
    float* s_z = sm + 1024 * 18;     // [32 rows][256 cols]

    const int tid = threadIdx.x;
    const int iy = tid >> 5, b = tid & 31;

    for (int idx = tid; idx < 16384; idx += 256) {
        int oc = idx >> 10, ab = idx & 1023;
        s_w[ab * 18 + oc] = wog[oc * 8192 + c * 1024 + ab];
    }

    float2 accP[64];
#pragma unroll
    for (int i = 0; i < 64; i++) accP[i] = make_float2(0.f, 0.f);

    const float* __restrict__ Zs = &g_Zall[t + 1][c][0];

    for (int k = 0; k < 8; k++) {
        __syncthreads();
        for (int idx = tid; idx < 8192; idx += 256) {
            int rl = idx >> 8, col = idx & 255;
            int grow = (rl >> 2) * 32 + k * 4 + (rl & 3);
            s_z[rl * 256 + col] = __ldcg(&Zs[grow * 256 + col]);
        }
        __syncthreads();
#pragma unroll
        for (int da = 0; da < 4; da++) {
            int a  = k * 4 + da;
            int rl = iy * 4 + da;
            float zv[8];
#pragma unroll
            for (int jw = 0; jw < 8; jw++) zv[jw] = s_z[rl * 256 + jw * 32 + b];
            const float* wrow = &s_w[(a * 32 + b) * 18];
            float2 wP[8];
#pragma unroll
            for (int p = 0; p < 8; p++) wP[p] = *(const float2*)&wrow[2 * p];
#pragma unroll
            for (int jw = 0; jw < 8; jw++) {
                float2 zp = make_float2(zv[jw], zv[jw]);
#pragma unroll
                for (int p = 0; p < 8; p++)
                    accP[jw * 8 + p] = fma2(accP[jw * 8 + p], zp, wP[p]);
            }
        }
    }

#pragma unroll
    for (int i = 0; i < 64; i++) {
#pragma unroll
        for (int d = 16; d >= 1; d >>= 1) {
            accP[i].x += __shfl_xor_sync(0xffffffffu, accP[i].x, d);
            accP[i].y += __shfl_xor_sync(0xffffffffu, accP[i].y, d);
        }
    }
#pragma unroll
    for (int i = 0; i < 64; i++) {
        if ((i >> 1) == b) {
            int jw = i >> 3, p = i & 7;
            atomicAdd(&yout[t * 1024 + (2 * p) * 64 + iy * 8 + jw], accP[i].x);
            atomicAdd(&yout[t * 1024 + (2 * p + 1) * 64 + iy * 8 + jw], accP[i].y);
        }
    }
}

#define RO_SMEM ((1024 * 18 + 32 * 256) * 4)

// ---------------- launcher (graph-capturable, alloc-free) ----------------
extern "C" void kernel_launch(void* const* d_in, const int* in_sizes, int n_in,
                              void* d_out, int out_size)
{
    const float* X           = (const float*)d_in[0];  // [128,512]
    const float* W_embed     = (const float*)d_in[1];  // [2048,512]
    const float* mask_coarse = (const float*)d_in[2];  // [16,16]
    const float* mask_fine   = (const float*)d_in[3];  // [256,256]
    const float* W_deconv    = (const float*)d_in[4];  // [8,8,16,16]
    const float* w1          = (const float*)d_in[5];  // [8,1,3,3]
    const float* w2          = (const float*)d_in[6];  // [8,1,5,5]
    const float* w_out       = (const float*)d_in[7];  // [16,8,32,32]
    const float* b_out       = (const float*)d_in[8];  // [16]
    float* y = (float*)d_out;                          // [128,1024]

    cudaFuncSetAttribute(k_readout, cudaFuncAttributeMaxDynamicSharedMemorySize,
                         RO_SMEM);

    k_transpose<<<dim3(64, 16), dim3(32, 8)>>>(W_embed);
    k_embed<<<dim3(8, 8), 256>>>(X, mask_coarse);
    k_udeconv<<<dim3(T_STEPS, NCH, 16), 256>>>(W_deconv, mask_fine);
    k_init_out<<<512, 256>>>(y, b_out);
    k_zero<<<2048, 256>>>();
    k_scan<<<256, 256>>>(w1, w2);
    k_readout<<<dim3(T_STEPS, NCH), 256, RO_SMEM>>>(w_out, y);
}